// round 3
// baseline (speedup 1.0000x reference)
#include <cuda_runtime.h>
#include <cuda_bf16.h>
#include <cstdint>

// ---------------- problem dims (compile-time) ----------------
#define BB   2
#define SS   1024
#define DD   1024
#define HH   16
#define DHH  64
#define DFFN 4096
#define LLAY 2
#define VV   32000
#define GSZ  128
#define MM   (BB*SS)          // 2048 rows of activations

// ---------------- canonical ternary weight buffer ----------------
// offsets (in elements) into g_w8
#define W_EMB   0L
#define W_Q     (W_EMB  + (long)VV*DD)                  // 32,768,000
#define W_K     (W_Q    + (long)LLAY*DD*DD)
#define W_V     (W_K    + (long)LLAY*DD*DD)
#define W_O     (W_V    + (long)LLAY*DD*DD)
#define W_GATE  (W_O    + (long)LLAY*DD*DD)
#define W_UP    (W_GATE + (long)LLAY*DFFN*DD)
#define W_DOWN  (W_UP   + (long)LLAY*DFFN*DD)
#define W_HEAD  (W_DOWN + (long)LLAY*DD*DFFN)
#define W_TOTAL (W_HEAD + (long)VV*DD)

__device__ int8_t g_w8[W_TOTAL];
__device__ int    g_wtype;        // 0=int8, 1=int32, 2=float32, 3=bf16

// ---------------- scratch (__device__ globals, no allocs) ----------------
__device__ float g_x[MM*DD];
__device__ float g_h[MM*DD];
__device__ float g_q[MM*DD];
__device__ float g_k[MM*DD];
__device__ float g_v[MM*DD];
__device__ float g_o[MM*DD];
__device__ float g_g[MM*DFFN];
__device__ float g_u[MM*DFFN];

// ---------------- dtype probe: sniff emb_t byte pattern ----------------
__global__ void probe_kernel(const void* raw) {
    if (threadIdx.x != 0) return;
    const unsigned* pw = (const unsigned*)raw;
    bool is_i32 = true;
    for (int i = 0; i < 256; i++) {
        unsigned w = pw[i];
        if (!(w == 0u || w == 1u || w == 0xFFFFFFFFu)) { is_i32 = false; break; }
    }
    if (is_i32) { g_wtype = 1; return; }
    bool is_f32 = true;
    for (int i = 0; i < 256; i++) {
        unsigned w = pw[i];
        if (!(w == 0u || w == 0x3F800000u || w == 0xBF800000u)) { is_f32 = false; break; }
    }
    if (is_f32) { g_wtype = 2; return; }
    const unsigned short* ph = (const unsigned short*)raw;
    bool is_b16 = true;
    for (int i = 0; i < 512; i++) {
        unsigned short w = ph[i];
        if (!(w == 0u || w == 0x3F80u || w == 0xBF80u)) { is_b16 = false; break; }
    }
    g_wtype = is_b16 ? 3 : 0;
}

// ---------------- canonicalize one ternary tensor into g_w8 ----------------
__global__ void convert_w_kernel(const void* __restrict__ src, long off, long n) {
    int t = g_wtype;
    long stride = (long)gridDim.x * blockDim.x;
    for (long i = (long)blockIdx.x * blockDim.x + threadIdx.x; i < n; i += stride) {
        int8_t v;
        if (t == 1)      v = (int8_t)((const int*)src)[i];
        else if (t == 2) v = (int8_t)(int)((const float*)src)[i];
        else if (t == 3) v = (int8_t)(int)__bfloat162float(((const __nv_bfloat16*)src)[i]);
        else             v = ((const int8_t*)src)[i];
        g_w8[off + i] = v;
    }
}

// ---------------- embedding: dequant gather ----------------
__global__ void embed_kernel(const int* __restrict__ ids,
                             const int8_t* __restrict__ et,
                             const float* __restrict__ es,
                             float* __restrict__ x) {
    int m  = blockIdx.x;
    int id = ids[m];
    long base = (long)id * DD;
    for (int d = threadIdx.x; d < DD; d += blockDim.x)
        x[(long)m * DD + d] = (float)et[base + d] * es[(base + d) >> 7];
}

// ---------------- rmsnorm ----------------
__global__ void rmsnorm_kernel(const float* __restrict__ x,
                               const float* __restrict__ w,
                               float* __restrict__ out) {
    int m = blockIdx.x;
    const float* xr = x + (long)m * DD;
    float ss = 0.f;
    for (int d = threadIdx.x; d < DD; d += blockDim.x) { float v = xr[d]; ss += v * v; }
    __shared__ float red[256];
    red[threadIdx.x] = ss; __syncthreads();
    #pragma unroll
    for (int st = 128; st > 0; st >>= 1) {
        if (threadIdx.x < st) red[threadIdx.x] += red[threadIdx.x + st];
        __syncthreads();
    }
    float r = rsqrtf(red[0] * (1.0f / DD) + 1e-6f);
    for (int d = threadIdx.x; d < DD; d += blockDim.x)
        out[(long)m * DD + d] = xr[d] * r * w[d];
}

// ---------------- ternary GEMM:  C[M,N] (+)= A[M,K] @ (W[N,K]*scale)^T ----------------
template <bool ACC>
__global__ __launch_bounds__(256)
void gemm_tern(const float* __restrict__ A, const int8_t* __restrict__ W,
               const float* __restrict__ sc, float* __restrict__ C,
               int M, int N, int K) {
    __shared__ __align__(16) float As[8][128];
    __shared__ __align__(16) float Bs[8][128];
    int tid = threadIdx.x;
    int bm = blockIdx.y * 128, bn = blockIdx.x * 128;
    int tx = tid & 15, ty = tid >> 4;
    int arow = tid >> 1;           // 0..127
    int acol = (tid & 1) * 4;      // 0 or 4
    int Kg = K >> 7;
    float acc[8][8];
    #pragma unroll
    for (int i = 0; i < 8; i++)
        #pragma unroll
        for (int j = 0; j < 8; j++) acc[i][j] = 0.f;

    for (int k0 = 0; k0 < K; k0 += 8) {
        float4 av = *(const float4*)(A + (long)(bm + arow) * K + k0 + acol);
        As[acol + 0][arow] = av.x; As[acol + 1][arow] = av.y;
        As[acol + 2][arow] = av.z; As[acol + 3][arow] = av.w;
        int n = bn + arow;
        unsigned int wv = *(const unsigned int*)(W + (long)n * K + k0 + acol);
        float s = sc[(long)n * Kg + (k0 >> 7)];
        Bs[acol + 0][arow] = (float)((int8_t)(wv      )) * s;
        Bs[acol + 1][arow] = (float)((int8_t)(wv >>  8)) * s;
        Bs[acol + 2][arow] = (float)((int8_t)(wv >> 16)) * s;
        Bs[acol + 3][arow] = (float)((int8_t)(wv >> 24)) * s;
        __syncthreads();
        #pragma unroll
        for (int kk = 0; kk < 8; kk++) {
            float a[8], b[8];
            float4 a0 = *(const float4*)&As[kk][ty * 8];
            float4 a1 = *(const float4*)&As[kk][ty * 8 + 4];
            float4 b0 = *(const float4*)&Bs[kk][tx * 8];
            float4 b1 = *(const float4*)&Bs[kk][tx * 8 + 4];
            a[0]=a0.x;a[1]=a0.y;a[2]=a0.z;a[3]=a0.w;a[4]=a1.x;a[5]=a1.y;a[6]=a1.z;a[7]=a1.w;
            b[0]=b0.x;b[1]=b0.y;b[2]=b0.z;b[3]=b0.w;b[4]=b1.x;b[5]=b1.y;b[6]=b1.z;b[7]=b1.w;
            #pragma unroll
            for (int i = 0; i < 8; i++)
                #pragma unroll
                for (int j = 0; j < 8; j++)
                    acc[i][j] += a[i] * b[j];
        }
        __syncthreads();
    }
    #pragma unroll
    for (int i = 0; i < 8; i++) {
        long row = bm + ty * 8 + i;
        #pragma unroll
        for (int j = 0; j < 8; j++) {
            long idx = row * N + bn + tx * 8 + j;
            C[idx] = (ACC ? C[idx] : 0.f) + acc[i][j];
        }
    }
}

// ---------------- fused causal attention: one block per (b,h,query row) ----------------
#define ATH 128
__global__ __launch_bounds__(ATH)
void attn_kernel(const float* __restrict__ q, const float* __restrict__ k,
                 const float* __restrict__ v, const float* __restrict__ h,
                 const float* __restrict__ alpha, float* __restrict__ o) {
    int r  = blockIdx.x;
    int bh = r >> 10;
    int s  = r & (SS - 1);
    int b  = bh >> 4, hh = bh & 15;
    int n  = s + 1;
    __shared__ float qs[64];
    __shared__ float scs[SS];
    __shared__ float red[ATH];
    int tid = threadIdx.x;

    const float* qrow = q + (long)(b * SS + s) * DD + hh * 64;
    if (tid < 64) qs[tid] = qrow[tid];
    __syncthreads();

    const float* kbase = k + (long)b * SS * DD + hh * 64;
    float mx = -3.4e38f;
    for (int t = tid; t < n; t += ATH) {
        const float* krow = kbase + (long)t * DD;
        float acc = 0.f;
        #pragma unroll 16
        for (int d = 0; d < 64; d++) acc += qs[d] * krow[d];
        acc *= 0.125f;
        scs[t] = acc;
        mx = fmaxf(mx, acc);
    }
    red[tid] = mx; __syncthreads();
    #pragma unroll
    for (int st = ATH / 2; st > 0; st >>= 1) {
        if (tid < st) red[tid] = fmaxf(red[tid], red[tid + st]);
        __syncthreads();
    }
    mx = red[0]; __syncthreads();

    float sum = 0.f;
    for (int t = tid; t < n; t += ATH) {
        float e = expf(scs[t] - mx);
        scs[t] = e;
        sum += e;
    }
    red[tid] = sum; __syncthreads();
    #pragma unroll
    for (int st = ATH / 2; st > 0; st >>= 1) {
        if (tid < st) red[tid] += red[tid + st];
        __syncthreads();
    }
    float inv = 1.f / red[0];

    if (tid < 64) {
        int d = tid;
        const float* vbase = v + (long)b * SS * DD + hh * 64 + d;
        float acc = 0.f;
        for (int t = 0; t < n; t++) acc += scs[t] * vbase[(long)t * DD];
        long idx = (long)(b * SS + s) * DD + hh * 64 + d;
        o[idx] = acc * inv + alpha[hh] * h[idx];
    }
}

// ---------------- silu(g) * u -> g ----------------
__global__ void silumul_kernel(float* __restrict__ g, const float* __restrict__ u) {
    long i = (long)blockIdx.x * 256 + threadIdx.x;
    float x = g[i];
    g[i] = x / (1.f + expf(-x)) * u[i];
}

// ---------------- host launcher ----------------
extern "C" void kernel_launch(void* const* d_in, const int* in_sizes, int n_in,
                              void* d_out, int out_size) {
    (void)in_sizes; (void)n_in; (void)out_size;
    const int*   ids   = (const int*)  d_in[0];
    const void*  emb_t = d_in[1];
    const float* emb_s = (const float*)d_in[2];
    const void*  qt = d_in[3];  const float* qs = (const float*)d_in[4];
    const void*  kt = d_in[5];  const float* ks = (const float*)d_in[6];
    const void*  vt = d_in[7];  const float* vs = (const float*)d_in[8];
    const void*  ot = d_in[9];  const float* os = (const float*)d_in[10];
    const void*  gt = d_in[11]; const float* gs = (const float*)d_in[12];
    const void*  ut = d_in[13]; const float* us = (const float*)d_in[14];
    const void*  dt = d_in[15]; const float* ds = (const float*)d_in[16];
    const float* wa    = (const float*)d_in[17];
    const float* wm    = (const float*)d_in[18];
    const float* alpha = (const float*)d_in[19];
    const float* wf    = (const float*)d_in[20];
    const void*  ht = d_in[21]; const float* hs = (const float*)d_in[22];
    float* out = (float*)d_out;

    float *x, *h, *q, *k, *v, *o, *g, *u; int8_t* w8;
    cudaGetSymbolAddress((void**)&x, g_x);
    cudaGetSymbolAddress((void**)&h, g_h);
    cudaGetSymbolAddress((void**)&q, g_q);
    cudaGetSymbolAddress((void**)&k, g_k);
    cudaGetSymbolAddress((void**)&v, g_v);
    cudaGetSymbolAddress((void**)&o, g_o);
    cudaGetSymbolAddress((void**)&g, g_g);
    cudaGetSymbolAddress((void**)&u, g_u);
    cudaGetSymbolAddress((void**)&w8, g_w8);

    // --- canonicalize ternary weights (dtype-agnostic) ---
    probe_kernel<<<1, 32>>>(emb_t);
    const int CB = 1024, CT = 256;
    convert_w_kernel<<<CB, CT>>>(emb_t, W_EMB,  (long)VV * DD);
    convert_w_kernel<<<CB, CT>>>(qt,    W_Q,    (long)LLAY * DD * DD);
    convert_w_kernel<<<CB, CT>>>(kt,    W_K,    (long)LLAY * DD * DD);
    convert_w_kernel<<<CB, CT>>>(vt,    W_V,    (long)LLAY * DD * DD);
    convert_w_kernel<<<CB, CT>>>(ot,    W_O,    (long)LLAY * DD * DD);
    convert_w_kernel<<<CB, CT>>>(gt,    W_GATE, (long)LLAY * DFFN * DD);
    convert_w_kernel<<<CB, CT>>>(ut,    W_UP,   (long)LLAY * DFFN * DD);
    convert_w_kernel<<<CB, CT>>>(dt,    W_DOWN, (long)LLAY * DD * DFFN);
    convert_w_kernel<<<CB, CT>>>(ht,    W_HEAD, (long)VV * DD);

    embed_kernel<<<MM, 256>>>(ids, w8 + W_EMB, emb_s, x);

    dim3 gDD(DD / 128, MM / 128);
    dim3 gFF(DFFN / 128, MM / 128);
    const long wstrD = (long)DD * DD;   const long sstrD = (long)DD * DD / GSZ;
    const long wstrF = (long)DFFN * DD; const long sstrF = (long)DFFN * DD / GSZ;

    for (int l = 0; l < LLAY; l++) {
        rmsnorm_kernel<<<MM, 256>>>(x, wa + (long)l * DD, h);
        gemm_tern<false><<<gDD, 256>>>(h, w8 + W_Q + l * wstrD, qs + l * sstrD, q, MM, DD, DD);
        gemm_tern<false><<<gDD, 256>>>(h, w8 + W_K + l * wstrD, ks + l * sstrD, k, MM, DD, DD);
        gemm_tern<false><<<gDD, 256>>>(h, w8 + W_V + l * wstrD, vs + l * sstrD, v, MM, DD, DD);
        attn_kernel<<<BB * HH * SS, ATH>>>(q, k, v, h, alpha + (long)l * HH, o);
        gemm_tern<true><<<gDD, 256>>>(o, w8 + W_O + l * wstrD, os + l * sstrD, x, MM, DD, DD);
        rmsnorm_kernel<<<MM, 256>>>(x, wm + (long)l * DD, h);
        gemm_tern<false><<<gFF, 256>>>(h, w8 + W_GATE + l * wstrF, gs + l * sstrF, g, MM, DFFN, DD);
        gemm_tern<false><<<gFF, 256>>>(h, w8 + W_UP   + l * wstrF, us + l * sstrF, u, MM, DFFN, DD);
        silumul_kernel<<<(MM * DFFN) / 256, 256>>>(g, u);
        gemm_tern<true><<<gDD, 256>>>(g, w8 + W_DOWN + l * wstrF, ds + l * sstrF, x, MM, DD, DFFN);
    }

    rmsnorm_kernel<<<MM, 256>>>(x, wf, h);
    gemm_tern<false><<<dim3(VV / 128, MM / 128), 256>>>(h, w8 + W_HEAD, hs, out, MM, VV, DD);
}

// round 4
// speedup vs baseline: 1.5544x; 1.5544x over previous
#include <cuda_runtime.h>
#include <cuda_bf16.h>
#include <cstdint>

using bf16 = __nv_bfloat16;

// ---------------- problem dims ----------------
#define BB   2
#define SS   1024
#define DD   1024
#define HH   16
#define DFFN 4096
#define LLAY 2
#define VV   32000
#define MM   (BB*SS)

// ---------------- bf16 weight buffer layout (elements) ----------------
// per-layer QKV packed contiguous so QKV runs as one N=3072 GEMM; gate+up packed for N=8192.
#define OQKV 0L                                    // [L][3*DD*DD]
#define OO   (OQKV + (long)LLAY*3*DD*DD)           // [L][DD*DD]
#define OGU  (OO   + (long)LLAY*DD*DD)             // [L][2*DFFN*DD]
#define ODW  (OGU  + (long)LLAY*2*DFFN*DD)         // [L][DD*DFFN]
#define OHD  (ODW  + (long)LLAY*DD*DFFN)           // [VV*DD]
#define WTOT (OHD  + (long)VV*DD)                  // 66,322,432

__device__ bf16 g_wb[2*WTOT];   // [hi | lo]
__device__ int  g_wtype;        // 0=int8 1=int32 2=f32 3=bf16

// ---------------- activation scratch ----------------
__device__ float g_x[MM*DD];
__device__ float g_h[MM*DD];
__device__ float g_qkv[(size_t)MM*3*DD];
__device__ float g_gu[(size_t)MM*2*DFFN];
__device__ bf16  g_hhi[MM*DD],  g_hlo[MM*DD];
__device__ bf16  g_ohi[MM*DD],  g_olo[MM*DD];
__device__ bf16  g_ghi[(size_t)MM*DFFN], g_glo[(size_t)MM*DFFN];

// ---------------- dtype probe ----------------
__global__ void probe_kernel(const void* raw) {
    if (threadIdx.x != 0) return;
    const unsigned* pw = (const unsigned*)raw;
    bool is_i32 = true;
    for (int i = 0; i < 256; i++) {
        unsigned w = pw[i];
        if (!(w == 0u || w == 1u || w == 0xFFFFFFFFu)) { is_i32 = false; break; }
    }
    if (is_i32) { g_wtype = 1; return; }
    bool is_f32 = true;
    for (int i = 0; i < 256; i++) {
        unsigned w = pw[i];
        if (!(w == 0u || w == 0x3F800000u || w == 0xBF800000u)) { is_f32 = false; break; }
    }
    if (is_f32) { g_wtype = 2; return; }
    const unsigned short* ph = (const unsigned short*)raw;
    bool is_b16 = true;
    for (int i = 0; i < 512; i++) {
        unsigned short w = ph[i];
        if (!(w == 0u || w == 0x3F80u || w == 0xBF80u)) { is_b16 = false; break; }
    }
    g_wtype = is_b16 ? 3 : 0;
}

__device__ __forceinline__ float load_tern(const void* p, long i, int t) {
    if (t == 1) return (float)((const int*)p)[i];
    if (t == 2) return ((const float*)p)[i];
    if (t == 3) return __bfloat162float(((const bf16*)p)[i]);
    return (float)((const int8_t*)p)[i];
}

// ---------------- weight convert: dequant + fold scale + hi/lo split ----------------
// scale group = 128 consecutive elements of the flattened [.., K] tensor => sc[i>>7]
__global__ void convert_wb(const void* __restrict__ src, const float* __restrict__ sc,
                           long srcOff, long dstOff, long n) {
    int t = g_wtype;
    long stride = (long)gridDim.x * blockDim.x;
    for (long i = (long)blockIdx.x * blockDim.x + threadIdx.x; i < n; i += stride) {
        float w = load_tern(src, srcOff + i, t) * sc[(srcOff + i) >> 7];
        bf16 hi = __float2bfloat16(w);
        g_wb[dstOff + i]        = hi;
        g_wb[WTOT + dstOff + i] = __float2bfloat16(w - __bfloat162float(hi));
    }
}

// ---------------- embedding: dequant gather from raw dtype ----------------
__global__ void embed_kernel(const int* __restrict__ ids, const void* __restrict__ et,
                             const float* __restrict__ es, float* __restrict__ x) {
    int t = g_wtype;
    int m = blockIdx.x;
    long base = (long)ids[m] * DD;
    for (int d = threadIdx.x; d < DD; d += blockDim.x) {
        long idx = base + d;
        x[(long)m * DD + d] = load_tern(et, idx, t) * es[idx >> 7];
    }
}

// ---------------- rmsnorm + hi/lo split ----------------
__global__ void rmsnorm_split(const float* __restrict__ x, const float* __restrict__ w,
                              float* __restrict__ h, bf16* __restrict__ hi, bf16* __restrict__ lo) {
    int m = blockIdx.x;
    const float* xr = x + (long)m * DD;
    float ss = 0.f;
    for (int d = threadIdx.x; d < DD; d += blockDim.x) { float v = xr[d]; ss += v * v; }
    __shared__ float red[256];
    red[threadIdx.x] = ss; __syncthreads();
    #pragma unroll
    for (int st = 128; st > 0; st >>= 1) {
        if (threadIdx.x < st) red[threadIdx.x] += red[threadIdx.x + st];
        __syncthreads();
    }
    float r = rsqrtf(red[0] * (1.0f / DD) + 1e-6f);
    for (int d = threadIdx.x; d < DD; d += blockDim.x) {
        long i = (long)m * DD + d;
        float y = xr[d] * r * w[d];
        if (h) h[i] = y;
        bf16 yh = __float2bfloat16(y);
        hi[i] = yh;
        lo[i] = __float2bfloat16(y - __bfloat162float(yh));
    }
}

// ---------------- mma.sync bf16 helpers ----------------
__device__ __forceinline__ void cpa16(uint32_t d, const void* s) {
    asm volatile("cp.async.ca.shared.global [%0], [%1], 16;\n" :: "r"(d), "l"(s));
}
__device__ __forceinline__ void ldsm4(uint32_t* r, uint32_t a) {
    asm volatile("ldmatrix.sync.aligned.m8n8.x4.shared.b16 {%0,%1,%2,%3},[%4];"
                 : "=r"(r[0]), "=r"(r[1]), "=r"(r[2]), "=r"(r[3]) : "r"(a));
}
__device__ __forceinline__ void ldsm2(uint32_t* r, uint32_t a) {
    asm volatile("ldmatrix.sync.aligned.m8n8.x2.shared.b16 {%0,%1},[%2];"
                 : "=r"(r[0]), "=r"(r[1]) : "r"(a));
}
__device__ __forceinline__ void mma16816(float* c, const uint32_t* a, const uint32_t* b) {
    asm volatile("mma.sync.aligned.m16n8k16.row.col.f32.bf16.bf16.f32 "
                 "{%0,%1,%2,%3},{%4,%5,%6,%7},{%8,%9},{%0,%1,%2,%3};"
                 : "+f"(c[0]), "+f"(c[1]), "+f"(c[2]), "+f"(c[3])
                 : "r"(a[0]), "r"(a[1]), "r"(a[2]), "r"(a[3]), "r"(b[0]), "r"(b[1]));
}

// ---------------- fused 3-product GEMM:  C (+)= Ahi·Bhi^T + Ahi·Blo^T + Alo·Bhi^T ----------------
// BM=BN=128, BK=32, 256 threads (8 warps as 2x4, warp tile 64x32), double-buffered cp.async.
// Smem per stage: Ah|Al|Bh|Bl each 128x40 bf16 (pad->conflict-free ldmatrix). 81920 B total.
#define STG_B 40960
#define AH_O  0
#define AL_O  10240
#define BH_O  20480
#define BL_O  30720

template<bool ACCF>
__global__ __launch_bounds__(256)
void gemm3_kernel(const bf16* __restrict__ Ah, const bf16* __restrict__ Al,
                  const bf16* __restrict__ Bh, const bf16* __restrict__ Bl,
                  float* __restrict__ C, int M, int N, int K) {
    extern __shared__ char smem_raw[];
    const uint32_t sbase = (uint32_t)__cvta_generic_to_shared(smem_raw);
    const int tid = threadIdx.x;
    const int lane = tid & 31, wid = tid >> 5;
    const int wm = wid >> 2, wn = wid & 3;
    const int bm = blockIdx.y * 128, bn = blockIdx.x * 128;

    const int r0 = tid >> 2, cc = (tid & 3) * 8;  // rows r0, r0+64

    // frag smem element offsets (within one 128x40 matrix)
    int aoffE[4], boffE[4];
    {
        int r = lane & 15, kh = (lane >> 4) * 8;
        #pragma unroll
        for (int mi = 0; mi < 4; mi++) aoffE[mi] = (wm * 64 + mi * 16 + r) * 40 + kh;
        #pragma unroll
        for (int ni = 0; ni < 4; ni++) boffE[ni] = (wn * 32 + ni * 8 + (r & 7)) * 40 + ((r >> 3) * 8);
    }

    float acc[4][4][4];
    #pragma unroll
    for (int i = 0; i < 4; i++)
        #pragma unroll
        for (int j = 0; j < 4; j++) { acc[i][j][0]=0.f; acc[i][j][1]=0.f; acc[i][j][2]=0.f; acc[i][j][3]=0.f; }

    auto load_stage = [&](int st, int k0) {
        uint32_t sb = sbase + st * STG_B;
        uint32_t d0 = r0 * 80 + cc * 2, d1 = (r0 + 64) * 80 + cc * 2;
        const size_t ga0 = (size_t)(bm + r0) * K + k0 + cc;
        const size_t ga1 = (size_t)(bm + r0 + 64) * K + k0 + cc;
        const size_t gb0 = (size_t)(bn + r0) * K + k0 + cc;
        const size_t gb1 = (size_t)(bn + r0 + 64) * K + k0 + cc;
        cpa16(sb + AH_O + d0, Ah + ga0);  cpa16(sb + AH_O + d1, Ah + ga1);
        cpa16(sb + AL_O + d0, Al + ga0);  cpa16(sb + AL_O + d1, Al + ga1);
        cpa16(sb + BH_O + d0, Bh + gb0);  cpa16(sb + BH_O + d1, Bh + gb1);
        cpa16(sb + BL_O + d0, Bl + gb0);  cpa16(sb + BL_O + d1, Bl + gb1);
    };

    const int KT = K >> 5;
    load_stage(0, 0);
    asm volatile("cp.async.commit_group;\n" ::: "memory");

    for (int kt = 0; kt < KT; kt++) {
        asm volatile("cp.async.wait_group 0;\n" ::: "memory");
        __syncthreads();
        if (kt + 1 < KT) load_stage((kt + 1) & 1, (kt + 1) << 5);
        asm volatile("cp.async.commit_group;\n" ::: "memory");

        uint32_t sb = sbase + (kt & 1) * STG_B;
        #pragma unroll
        for (int kk = 0; kk < 2; kk++) {
            const int kb = kk * 32;   // 16 elems * 2B
            uint32_t ah[4][4], al[4][4], bh[4][2], bl[4][2];
            #pragma unroll
            for (int mi = 0; mi < 4; mi++) {
                ldsm4(ah[mi], sb + AH_O + aoffE[mi] * 2 + kb);
                ldsm4(al[mi], sb + AL_O + aoffE[mi] * 2 + kb);
            }
            #pragma unroll
            for (int ni = 0; ni < 4; ni++) {
                ldsm2(bh[ni], sb + BH_O + boffE[ni] * 2 + kb);
                ldsm2(bl[ni], sb + BL_O + boffE[ni] * 2 + kb);
            }
            #pragma unroll
            for (int mi = 0; mi < 4; mi++)
                #pragma unroll
                for (int ni = 0; ni < 4; ni++) {
                    mma16816(acc[mi][ni], ah[mi], bh[ni]);
                    mma16816(acc[mi][ni], ah[mi], bl[ni]);
                    mma16816(acc[mi][ni], al[mi], bh[ni]);
                }
        }
    }

    // epilogue
    #pragma unroll
    for (int mi = 0; mi < 4; mi++) {
        int row = bm + wm * 64 + mi * 16 + (lane >> 2);
        #pragma unroll
        for (int ni = 0; ni < 4; ni++) {
            int col = bn + wn * 32 + ni * 8 + (lane & 3) * 2;
            float* p0 = C + (size_t)row * N + col;
            float* p1 = p0 + (size_t)8 * N;
            if (ACCF) {
                p0[0] += acc[mi][ni][0]; p0[1] += acc[mi][ni][1];
                p1[0] += acc[mi][ni][2]; p1[1] += acc[mi][ni][3];
            } else {
                p0[0] = acc[mi][ni][0]; p0[1] = acc[mi][ni][1];
                p1[0] = acc[mi][ni][2]; p1[1] = acc[mi][ni][3];
            }
        }
    }
}

// ---------------- fused causal attention (reads packed qkv, writes split o) ----------------
#define ATH 128
__global__ __launch_bounds__(ATH)
void attn_kernel(const float* __restrict__ qkv, const float* __restrict__ h,
                 const float* __restrict__ alpha, bf16* __restrict__ ohi, bf16* __restrict__ olo) {
    int r  = blockIdx.x;
    int bh = r >> 10;
    int s  = r & (SS - 1);
    int b  = bh >> 4, hh = bh & 15;
    int n  = s + 1;
    __shared__ float qs[64];
    __shared__ float scs[SS];
    __shared__ float red[ATH];
    int tid = threadIdx.x;

    const float* qrow = qkv + (size_t)(b * SS + s) * 3072 + hh * 64;
    if (tid < 64) qs[tid] = qrow[tid];
    __syncthreads();

    const float* kbase = qkv + (size_t)b * SS * 3072 + 1024 + hh * 64;
    float mx = -3.4e38f;
    for (int t = tid; t < n; t += ATH) {
        const float* krow = kbase + (size_t)t * 3072;
        float acc = 0.f;
        #pragma unroll 16
        for (int d = 0; d < 64; d++) acc += qs[d] * krow[d];
        acc *= 0.125f;
        scs[t] = acc;
        mx = fmaxf(mx, acc);
    }
    red[tid] = mx; __syncthreads();
    #pragma unroll
    for (int st = ATH / 2; st > 0; st >>= 1) {
        if (tid < st) red[tid] = fmaxf(red[tid], red[tid + st]);
        __syncthreads();
    }
    mx = red[0]; __syncthreads();

    float sum = 0.f;
    for (int t = tid; t < n; t += ATH) {
        float e = expf(scs[t] - mx);
        scs[t] = e;
        sum += e;
    }
    red[tid] = sum; __syncthreads();
    #pragma unroll
    for (int st = ATH / 2; st > 0; st >>= 1) {
        if (tid < st) red[tid] += red[tid + st];
        __syncthreads();
    }
    float inv = 1.f / red[0];

    if (tid < 64) {
        int d = tid;
        const float* vbase = qkv + (size_t)b * SS * 3072 + 2048 + hh * 64 + d;
        float acc = 0.f;
        for (int t = 0; t < n; t++) acc += scs[t] * vbase[(size_t)t * 3072];
        long idx = (long)(b * SS + s) * DD + hh * 64 + d;
        float val = acc * inv + alpha[hh] * h[idx];
        bf16 vh = __float2bfloat16(val);
        ohi[idx] = vh;
        olo[idx] = __float2bfloat16(val - __bfloat162float(vh));
    }
}

// ---------------- silu(g)*u from packed gu, split to bf16 ----------------
__global__ void silumul_split(const float* __restrict__ gu, bf16* __restrict__ ghi, bf16* __restrict__ glo) {
    long i = (long)blockIdx.x * 256 + threadIdx.x;   // over MM*DFFN
    long m = i >> 12, j = i & 4095;
    float a = gu[(m << 13) + j];
    float u = gu[(m << 13) + 4096 + j];
    float val = a / (1.f + expf(-a)) * u;
    bf16 vh = __float2bfloat16(val);
    ghi[i] = vh;
    glo[i] = __float2bfloat16(val - __bfloat162float(vh));
}

// ---------------- host launcher ----------------
extern "C" void kernel_launch(void* const* d_in, const int* in_sizes, int n_in,
                              void* d_out, int out_size) {
    (void)in_sizes; (void)n_in; (void)out_size;
    const int*   ids   = (const int*)  d_in[0];
    const void*  emb_t = d_in[1];
    const float* emb_s = (const float*)d_in[2];
    const void*  qt = d_in[3];  const float* qs = (const float*)d_in[4];
    const void*  kt = d_in[5];  const float* ks = (const float*)d_in[6];
    const void*  vt = d_in[7];  const float* vs = (const float*)d_in[8];
    const void*  ot = d_in[9];  const float* os = (const float*)d_in[10];
    const void*  gt = d_in[11]; const float* gs = (const float*)d_in[12];
    const void*  ut = d_in[13]; const float* us = (const float*)d_in[14];
    const void*  dt = d_in[15]; const float* ds = (const float*)d_in[16];
    const float* wa    = (const float*)d_in[17];
    const float* wm    = (const float*)d_in[18];
    const float* alpha = (const float*)d_in[19];
    const float* wf    = (const float*)d_in[20];
    const void*  ht = d_in[21]; const float* hs = (const float*)d_in[22];
    float* out = (float*)d_out;

    float *x, *h, *qkv, *gu;
    bf16 *wb, *hhi, *hlo, *ohi, *olo, *ghi, *glo;
    cudaGetSymbolAddress((void**)&x,   g_x);
    cudaGetSymbolAddress((void**)&h,   g_h);
    cudaGetSymbolAddress((void**)&qkv, g_qkv);
    cudaGetSymbolAddress((void**)&gu,  g_gu);
    cudaGetSymbolAddress((void**)&wb,  g_wb);
    cudaGetSymbolAddress((void**)&hhi, g_hhi);
    cudaGetSymbolAddress((void**)&hlo, g_hlo);
    cudaGetSymbolAddress((void**)&ohi, g_ohi);
    cudaGetSymbolAddress((void**)&olo, g_olo);
    cudaGetSymbolAddress((void**)&ghi, g_ghi);
    cudaGetSymbolAddress((void**)&glo, g_glo);

    cudaFuncSetAttribute(gemm3_kernel<false>, cudaFuncAttributeMaxDynamicSharedMemorySize, 2 * STG_B);
    cudaFuncSetAttribute(gemm3_kernel<true>,  cudaFuncAttributeMaxDynamicSharedMemorySize, 2 * STG_B);

    // --- probe dtype + convert weights (dequant, fold scales, hi/lo split) ---
    probe_kernel<<<1, 32>>>(emb_t);
    const int CB = 2048, CT = 256;
    const long SZD = (long)DD * DD;          // 1,048,576
    const long SZF = (long)DFFN * DD;        // 4,194,304
    for (int l = 0; l < LLAY; l++) {
        convert_wb<<<CB, CT>>>(qt, qs, l * SZD, OQKV + (long)l * 3 * SZD,            SZD);
        convert_wb<<<CB, CT>>>(kt, ks, l * SZD, OQKV + (long)l * 3 * SZD + SZD,      SZD);
        convert_wb<<<CB, CT>>>(vt, vs, l * SZD, OQKV + (long)l * 3 * SZD + 2 * SZD,  SZD);
        convert_wb<<<CB, CT>>>(gt, gs, l * SZF, OGU  + (long)l * 2 * SZF,            SZF);
        convert_wb<<<CB, CT>>>(ut, us, l * SZF, OGU  + (long)l * 2 * SZF + SZF,      SZF);
    }
    convert_wb<<<CB, CT>>>(ot, os, 0, OO,  (long)LLAY * SZD);
    convert_wb<<<CB, CT>>>(dt, ds, 0, ODW, (long)LLAY * SZF);
    convert_wb<<<CB, CT>>>(ht, hs, 0, OHD, (long)VV * DD);

    embed_kernel<<<MM, 256>>>(ids, emb_t, emb_s, x);

    const bf16* WL = wb + WTOT;
    const size_t smem = 2 * STG_B;

    for (int l = 0; l < LLAY; l++) {
        long oqkv = OQKV + (long)l * 3 * SZD;
        long oo   = OO   + (long)l * SZD;
        long ogu  = OGU  + (long)l * 2 * SZF;
        long odw  = ODW  + (long)l * SZF;

        rmsnorm_split<<<MM, 256>>>(x, wa + (long)l * DD, h, hhi, hlo);
        gemm3_kernel<false><<<dim3(24, 16), 256, smem>>>(hhi, hlo, wb + oqkv, WL + oqkv, qkv, MM, 3 * DD, DD);
        attn_kernel<<<BB * HH * SS, ATH>>>(qkv, h, alpha + (long)l * HH, ohi, olo);
        gemm3_kernel<true><<<dim3(8, 16), 256, smem>>>(ohi, olo, wb + oo, WL + oo, x, MM, DD, DD);

        rmsnorm_split<<<MM, 256>>>(x, wm + (long)l * DD, nullptr, hhi, hlo);
        gemm3_kernel<false><<<dim3(64, 16), 256, smem>>>(hhi, hlo, wb + ogu, WL + ogu, gu, MM, 2 * DFFN, DD);
        silumul_split<<<(long)MM * DFFN / 256, 256>>>(gu, ghi, glo);
        gemm3_kernel<true><<<dim3(8, 16), 256, smem>>>(ghi, glo, wb + odw, WL + odw, x, MM, DD, DFFN);
    }

    rmsnorm_split<<<MM, 256>>>(x, wf, nullptr, hhi, hlo);
    gemm3_kernel<false><<<dim3(VV / 128, 16), 256, smem>>>(hhi, hlo, wb + OHD, WL + OHD, out, MM, VV, DD);
}

// round 9
// speedup vs baseline: 5.4705x; 3.5194x over previous
#include <cuda_runtime.h>
#include <cuda_bf16.h>
#include <cstdint>

using bf16 = __nv_bfloat16;

// ---------------- problem dims ----------------
#define BB   2
#define SS   1024
#define DD   1024
#define HH   16
#define DFFN 4096
#define LLAY 2
#define VV   32000
#define MM   (BB*SS)

// ---------------- bf16 weight buffer layout (elements) ----------------
#define OQKV 0L
#define OO   (OQKV + (long)LLAY*3*DD*DD)
#define OGU  (OO   + (long)LLAY*DD*DD)
#define ODW  (OGU  + (long)LLAY*2*DFFN*DD)
#define OHD  (ODW  + (long)LLAY*DD*DFFN)
#define WTOT (OHD  + (long)VV*DD)

__device__ bf16 g_wb[2*WTOT];   // [hi | lo]
__device__ int  g_wtype;

// ---------------- activation scratch ----------------
__device__ float g_x[MM*DD];
__device__ float g_h[MM*DD];
__device__ float g_qkv[(size_t)MM*3*DD];
__device__ float g_gu[(size_t)MM*2*DFFN];
__device__ bf16  g_hhi[MM*DD],  g_hlo[MM*DD];
__device__ bf16  g_ohi[MM*DD],  g_olo[MM*DD];
__device__ bf16  g_ghi[(size_t)MM*DFFN], g_glo[(size_t)MM*DFFN];

// ---------------- dtype probe ----------------
__global__ void probe_kernel(const void* raw) {
    if (threadIdx.x != 0) return;
    const unsigned* pw = (const unsigned*)raw;
    bool is_i32 = true;
    for (int i = 0; i < 256; i++) {
        unsigned w = pw[i];
        if (!(w == 0u || w == 1u || w == 0xFFFFFFFFu)) { is_i32 = false; break; }
    }
    if (is_i32) { g_wtype = 1; return; }
    bool is_f32 = true;
    for (int i = 0; i < 256; i++) {
        unsigned w = pw[i];
        if (!(w == 0u || w == 0x3F800000u || w == 0xBF800000u)) { is_f32 = false; break; }
    }
    if (is_f32) { g_wtype = 2; return; }
    const unsigned short* ph = (const unsigned short*)raw;
    bool is_b16 = true;
    for (int i = 0; i < 512; i++) {
        unsigned short w = ph[i];
        if (!(w == 0u || w == 0x3F80u || w == 0xBF80u)) { is_b16 = false; break; }
    }
    g_wtype = is_b16 ? 3 : 0;
}

__device__ __forceinline__ float load_tern(const void* p, long i, int t) {
    if (t == 1) return (float)((const int*)p)[i];
    if (t == 2) return ((const float*)p)[i];
    if (t == 3) return __bfloat162float(((const bf16*)p)[i]);
    return (float)((const int8_t*)p)[i];
}

// ---------------- weight convert: dequant + fold scale + hi/lo split ----------------
__global__ void convert_wb(const void* __restrict__ src, const float* __restrict__ sc,
                           long srcOff, long dstOff, long n) {
    int t = g_wtype;
    long stride = (long)gridDim.x * blockDim.x;
    for (long i = (long)blockIdx.x * blockDim.x + threadIdx.x; i < n; i += stride) {
        float w = load_tern(src, srcOff + i, t) * sc[(srcOff + i) >> 7];
        bf16 hi = __float2bfloat16(w);
        g_wb[dstOff + i]        = hi;
        g_wb[WTOT + dstOff + i] = __float2bfloat16(w - __bfloat162float(hi));
    }
}

// ---------------- embedding ----------------
__global__ void embed_kernel(const int* __restrict__ ids, const void* __restrict__ et,
                             const float* __restrict__ es, float* __restrict__ x) {
    int t = g_wtype;
    int m = blockIdx.x;
    long base = (long)ids[m] * DD;
    for (int d = threadIdx.x; d < DD; d += blockDim.x) {
        long idx = base + d;
        x[(long)m * DD + d] = load_tern(et, idx, t) * es[idx >> 7];
    }
}

// ---------------- rmsnorm + hi/lo split ----------------
__global__ void rmsnorm_split(const float* __restrict__ x, const float* __restrict__ w,
                              float* __restrict__ h, bf16* __restrict__ hi, bf16* __restrict__ lo) {
    int m = blockIdx.x;
    const float* xr = x + (long)m * DD;
    float ss = 0.f;
    for (int d = threadIdx.x; d < DD; d += blockDim.x) { float v = xr[d]; ss += v * v; }
    __shared__ float red[256];
    red[threadIdx.x] = ss; __syncthreads();
    #pragma unroll
    for (int st = 128; st > 0; st >>= 1) {
        if (threadIdx.x < st) red[threadIdx.x] += red[threadIdx.x + st];
        __syncthreads();
    }
    float r = rsqrtf(red[0] * (1.0f / DD) + 1e-6f);
    for (int d = threadIdx.x; d < DD; d += blockDim.x) {
        long i = (long)m * DD + d;
        float y = xr[d] * r * w[d];
        if (h) h[i] = y;
        bf16 yh = __float2bfloat16(y);
        hi[i] = yh;
        lo[i] = __float2bfloat16(y - __bfloat162float(yh));
    }
}

// ---------------- mma.sync bf16 helpers ----------------
__device__ __forceinline__ void cpa16(uint32_t d, const void* s) {
    asm volatile("cp.async.ca.shared.global [%0], [%1], 16;\n" :: "r"(d), "l"(s));
}
__device__ __forceinline__ void ldsm4(uint32_t* r, uint32_t a) {
    asm volatile("ldmatrix.sync.aligned.m8n8.x4.shared.b16 {%0,%1,%2,%3},[%4];"
                 : "=r"(r[0]), "=r"(r[1]), "=r"(r[2]), "=r"(r[3]) : "r"(a));
}
__device__ __forceinline__ void ldsm2(uint32_t* r, uint32_t a) {
    asm volatile("ldmatrix.sync.aligned.m8n8.x2.shared.b16 {%0,%1},[%2];"
                 : "=r"(r[0]), "=r"(r[1]) : "r"(a));
}
__device__ __forceinline__ void mma16816(float* c, const uint32_t* a, const uint32_t* b) {
    asm volatile("mma.sync.aligned.m16n8k16.row.col.f32.bf16.bf16.f32 "
                 "{%0,%1,%2,%3},{%4,%5,%6,%7},{%8,%9},{%0,%1,%2,%3};"
                 : "+f"(c[0]), "+f"(c[1]), "+f"(c[2]), "+f"(c[3])
                 : "r"(a[0]), "r"(a[1]), "r"(a[2]), "r"(a[3]), "r"(b[0]), "r"(b[1]));
}

// ---------------- fused 3-product GEMM:  C (+)= Ahi·Bhi^T + Ahi·Blo^T + Alo·Bhi^T ----------------
// BM=BN=128, BK=32, 256 threads (8 warps as 2x4, warp tile 64x32), double-buffered cp.async.
// 2 CTAs/SM; products scheduled sequentially to keep live frag regs at 32.
#define STG_B 40960
#define AH_O  0
#define AL_O  10240
#define BH_O  20480
#define BL_O  30720

template<bool ACCF>
__global__ __launch_bounds__(256, 2)
void gemm3_kernel(const bf16* __restrict__ Ah, const bf16* __restrict__ Al,
                  const bf16* __restrict__ Bh, const bf16* __restrict__ Bl,
                  float* __restrict__ C, int M, int N, int K) {
    extern __shared__ char smem_raw[];
    const uint32_t sbase = (uint32_t)__cvta_generic_to_shared(smem_raw);
    const int tid = threadIdx.x;
    const int lane = tid & 31, wid = tid >> 5;
    const int wm = wid >> 2, wn = wid & 3;
    const int bm = blockIdx.y * 128, bn = blockIdx.x * 128;

    const int r0 = tid >> 2, cc = (tid & 3) * 8;

    int aoffE[4], boffE[4];
    {
        int r = lane & 15, kh = (lane >> 4) * 8;
        #pragma unroll
        for (int mi = 0; mi < 4; mi++) aoffE[mi] = (wm * 64 + mi * 16 + r) * 40 + kh;
        #pragma unroll
        for (int ni = 0; ni < 4; ni++) boffE[ni] = (wn * 32 + ni * 8 + (r & 7)) * 40 + ((r >> 3) * 8);
    }

    float acc[4][4][4];
    #pragma unroll
    for (int i = 0; i < 4; i++)
        #pragma unroll
        for (int j = 0; j < 4; j++) { acc[i][j][0]=0.f; acc[i][j][1]=0.f; acc[i][j][2]=0.f; acc[i][j][3]=0.f; }

    auto load_stage = [&](int st, int k0) {
        uint32_t sb = sbase + st * STG_B;
        uint32_t d0 = r0 * 80 + cc * 2, d1 = (r0 + 64) * 80 + cc * 2;
        const size_t ga0 = (size_t)(bm + r0) * K + k0 + cc;
        const size_t ga1 = (size_t)(bm + r0 + 64) * K + k0 + cc;
        const size_t gb0 = (size_t)(bn + r0) * K + k0 + cc;
        const size_t gb1 = (size_t)(bn + r0 + 64) * K + k0 + cc;
        cpa16(sb + AH_O + d0, Ah + ga0);  cpa16(sb + AH_O + d1, Ah + ga1);
        cpa16(sb + AL_O + d0, Al + ga0);  cpa16(sb + AL_O + d1, Al + ga1);
        cpa16(sb + BH_O + d0, Bh + gb0);  cpa16(sb + BH_O + d1, Bh + gb1);
        cpa16(sb + BL_O + d0, Bl + gb0);  cpa16(sb + BL_O + d1, Bl + gb1);
    };

    const int KT = K >> 5;
    load_stage(0, 0);
    asm volatile("cp.async.commit_group;\n" ::: "memory");

    for (int kt = 0; kt < KT; kt++) {
        asm volatile("cp.async.wait_group 0;\n" ::: "memory");
        __syncthreads();
        if (kt + 1 < KT) load_stage((kt + 1) & 1, (kt + 1) << 5);
        asm volatile("cp.async.commit_group;\n" ::: "memory");

        uint32_t sb = sbase + (kt & 1) * STG_B;
        #pragma unroll
        for (int kk = 0; kk < 2; kk++) {
            const int kb = kk * 32;
            uint32_t ah[4][4], bh[4][2], bl[4][2];
            #pragma unroll
            for (int mi = 0; mi < 4; mi++) ldsm4(ah[mi], sb + AH_O + aoffE[mi] * 2 + kb);
            #pragma unroll
            for (int ni = 0; ni < 4; ni++) ldsm2(bh[ni], sb + BH_O + boffE[ni] * 2 + kb);
            #pragma unroll
            for (int ni = 0; ni < 4; ni++) ldsm2(bl[ni], sb + BL_O + boffE[ni] * 2 + kb);
            #pragma unroll
            for (int mi = 0; mi < 4; mi++)
                #pragma unroll
                for (int ni = 0; ni < 4; ni++) mma16816(acc[mi][ni], ah[mi], bh[ni]);
            #pragma unroll
            for (int mi = 0; mi < 4; mi++)
                #pragma unroll
                for (int ni = 0; ni < 4; ni++) mma16816(acc[mi][ni], ah[mi], bl[ni]);
            // reuse ah registers for Alo
            #pragma unroll
            for (int mi = 0; mi < 4; mi++) ldsm4(ah[mi], sb + AL_O + aoffE[mi] * 2 + kb);
            #pragma unroll
            for (int mi = 0; mi < 4; mi++)
                #pragma unroll
                for (int ni = 0; ni < 4; ni++) mma16816(acc[mi][ni], ah[mi], bh[ni]);
        }
    }

    #pragma unroll
    for (int mi = 0; mi < 4; mi++) {
        int row = bm + wm * 64 + mi * 16 + (lane >> 2);
        #pragma unroll
        for (int ni = 0; ni < 4; ni++) {
            int col = bn + wn * 32 + ni * 8 + (lane & 3) * 2;
            float* p0 = C + (size_t)row * N + col;
            float* p1 = p0 + (size_t)8 * N;
            if (ACCF) {
                p0[0] += acc[mi][ni][0]; p0[1] += acc[mi][ni][1];
                p1[0] += acc[mi][ni][2]; p1[1] += acc[mi][ni][3];
            } else {
                p0[0] = acc[mi][ni][0]; p0[1] = acc[mi][ni][1];
                p1[0] = acc[mi][ni][2]; p1[1] = acc[mi][ni][3];
            }
        }
    }
}

// ---------------- flash-style tiled causal attention ----------------
// grid (S/64, B*H), 256 threads as 16x16; each thread: 4 rows x 4 cols.
// smem: Qs,Ks,Vs,Ps each 64x65 f32 (dynamic, 66560 B).
__device__ __forceinline__ float rmax16(float v) {
    #pragma unroll
    for (int m = 1; m < 16; m <<= 1) v = fmaxf(v, __shfl_xor_sync(0xffffffffu, v, m));
    return v;
}
__device__ __forceinline__ float rsum16(float v) {
    #pragma unroll
    for (int m = 1; m < 16; m <<= 1) v += __shfl_xor_sync(0xffffffffu, v, m);
    return v;
}

__global__ __launch_bounds__(256)
void attn_flash(const float* __restrict__ qkv, const float* __restrict__ h,
                const float* __restrict__ alpha, bf16* __restrict__ ohi, bf16* __restrict__ olo) {
    extern __shared__ float sm[];
    float (*Qs)[65] = (float(*)[65])sm;
    float (*Ks)[65] = (float(*)[65])(sm + 64 * 65);
    float (*Vs)[65] = (float(*)[65])(sm + 2 * 64 * 65);
    float (*Ps)[65] = (float(*)[65])(sm + 3 * 64 * 65);

    int qt = blockIdx.x;            // query tile
    int bh = blockIdx.y;
    int b = bh >> 4, hh = bh & 15;
    int tid = threadIdx.x;
    int tx = tid & 15, ty = tid >> 4;

    const float* qb = qkv + (size_t)(b * SS + qt * 64) * 3072 + hh * 64;
    for (int i = tid; i < 64 * 64; i += 256)
        Qs[i >> 6][i & 63] = qb[(size_t)(i >> 6) * 3072 + (i & 63)];

    float m_run[4], l_run[4], O[4][4];
    #pragma unroll
    for (int i = 0; i < 4; i++) {
        m_run[i] = -3.4e38f; l_run[i] = 0.f;
        O[i][0] = O[i][1] = O[i][2] = O[i][3] = 0.f;
    }

    const float* kb = qkv + (size_t)b * SS * 3072 + 1024 + hh * 64;
    const float* vb = qkv + (size_t)b * SS * 3072 + 2048 + hh * 64;

    for (int kt = 0; kt <= qt; kt++) {
        __syncthreads();
        for (int i = tid; i < 64 * 64; i += 256) {
            int r = i >> 6, c = i & 63;
            size_t gr = (size_t)(kt * 64 + r) * 3072 + c;
            Ks[r][c] = kb[gr];
            Vs[r][c] = vb[gr];
        }
        __syncthreads();

        // scores: s[i][j] = 0.125 * Q[ty*4+i] . K[tx*4+j]
        float s[4][4];
        #pragma unroll
        for (int i = 0; i < 4; i++) { s[i][0]=0.f; s[i][1]=0.f; s[i][2]=0.f; s[i][3]=0.f; }
        #pragma unroll 8
        for (int d = 0; d < 64; d++) {
            float a[4], bv[4];
            #pragma unroll
            for (int i = 0; i < 4; i++) a[i]  = Qs[ty * 4 + i][d];
            #pragma unroll
            for (int j = 0; j < 4; j++) bv[j] = Ks[tx * 4 + j][d];
            #pragma unroll
            for (int i = 0; i < 4; i++)
                #pragma unroll
                for (int j = 0; j < 4; j++) s[i][j] += a[i] * bv[j];
        }
        if (kt == qt) {
            #pragma unroll
            for (int i = 0; i < 4; i++) {
                int row = ty * 4 + i;
                #pragma unroll
                for (int j = 0; j < 4; j++)
                    if (tx * 4 + j > row) s[i][j] = -3.4e38f;
        } }
        #pragma unroll
        for (int i = 0; i < 4; i++) {
            float tm = fmaxf(fmaxf(s[i][0] * 0.125f, s[i][1] * 0.125f),
                             fmaxf(s[i][2] * 0.125f, s[i][3] * 0.125f));
            tm = rmax16(tm);
            float m_new = fmaxf(m_run[i], tm);
            float fac = expf(m_run[i] - m_new);
            float rs = 0.f;
            #pragma unroll
            for (int j = 0; j < 4; j++) {
                float p = expf(s[i][j] * 0.125f - m_new);
                Ps[ty * 4 + i][tx * 4 + j] = p;
                rs += p;
            }
            rs = rsum16(rs);
            l_run[i] = l_run[i] * fac + rs;
            m_run[i] = m_new;
            #pragma unroll
            for (int j = 0; j < 4; j++) O[i][j] *= fac;
        }
        __syncthreads();

        // O += P . V
        #pragma unroll 8
        for (int t = 0; t < 64; t++) {
            float a[4], bv[4];
            #pragma unroll
            for (int i = 0; i < 4; i++) a[i]  = Ps[ty * 4 + i][t];
            #pragma unroll
            for (int j = 0; j < 4; j++) bv[j] = Vs[t][tx * 4 + j];
            #pragma unroll
            for (int i = 0; i < 4; i++)
                #pragma unroll
                for (int j = 0; j < 4; j++) O[i][j] += a[i] * bv[j];
        }
    }

    float ah = alpha[hh];
    #pragma unroll
    for (int i = 0; i < 4; i++) {
        float inv = 1.f / l_run[i];
        int row = qt * 64 + ty * 4 + i;
        #pragma unroll
        for (int j = 0; j < 4; j++) {
            long idx = (long)(b * SS + row) * DD + hh * 64 + tx * 4 + j;
            float val = O[i][j] * inv + ah * h[idx];
            bf16 vh = __float2bfloat16(val);
            ohi[idx] = vh;
            olo[idx] = __float2bfloat16(val - __bfloat162float(vh));
        }
    }
}

// ---------------- silu(g)*u, split ----------------
__global__ void silumul_split(const float* __restrict__ gu, bf16* __restrict__ ghi, bf16* __restrict__ glo) {
    long i = (long)blockIdx.x * 256 + threadIdx.x;
    long m = i >> 12, j = i & 4095;
    float a = gu[(m << 13) + j];
    float u = gu[(m << 13) + 4096 + j];
    float val = a / (1.f + expf(-a)) * u;
    bf16 vh = __float2bfloat16(val);
    ghi[i] = vh;
    glo[i] = __float2bfloat16(val - __bfloat162float(vh));
}

// ---------------- host launcher ----------------
extern "C" void kernel_launch(void* const* d_in, const int* in_sizes, int n_in,
                              void* d_out, int out_size) {
    (void)in_sizes; (void)n_in; (void)out_size;
    const int*   ids   = (const int*)  d_in[0];
    const void*  emb_t = d_in[1];
    const float* emb_s = (const float*)d_in[2];
    const void*  qt = d_in[3];  const float* qs = (const float*)d_in[4];
    const void*  kt = d_in[5];  const float* ks = (const float*)d_in[6];
    const void*  vt = d_in[7];  const float* vs = (const float*)d_in[8];
    const void*  ot = d_in[9];  const float* os = (const float*)d_in[10];
    const void*  gt = d_in[11]; const float* gs = (const float*)d_in[12];
    const void*  ut = d_in[13]; const float* us = (const float*)d_in[14];
    const void*  dt = d_in[15]; const float* ds = (const float*)d_in[16];
    const float* wa    = (const float*)d_in[17];
    const float* wm    = (const float*)d_in[18];
    const float* alpha = (const float*)d_in[19];
    const float* wf    = (const float*)d_in[20];
    const void*  ht = d_in[21]; const float* hs = (const float*)d_in[22];
    float* out = (float*)d_out;

    float *x, *h, *qkv, *gu;
    bf16 *wb, *hhi, *hlo, *ohi, *olo, *ghi, *glo;
    cudaGetSymbolAddress((void**)&x,   g_x);
    cudaGetSymbolAddress((void**)&h,   g_h);
    cudaGetSymbolAddress((void**)&qkv, g_qkv);
    cudaGetSymbolAddress((void**)&gu,  g_gu);
    cudaGetSymbolAddress((void**)&wb,  g_wb);
    cudaGetSymbolAddress((void**)&hhi, g_hhi);
    cudaGetSymbolAddress((void**)&hlo, g_hlo);
    cudaGetSymbolAddress((void**)&ohi, g_ohi);
    cudaGetSymbolAddress((void**)&olo, g_olo);
    cudaGetSymbolAddress((void**)&ghi, g_ghi);
    cudaGetSymbolAddress((void**)&glo, g_glo);

    cudaFuncSetAttribute(gemm3_kernel<false>, cudaFuncAttributeMaxDynamicSharedMemorySize, 2 * STG_B);
    cudaFuncSetAttribute(gemm3_kernel<true>,  cudaFuncAttributeMaxDynamicSharedMemorySize, 2 * STG_B);
    cudaFuncSetAttribute(attn_flash, cudaFuncAttributeMaxDynamicSharedMemorySize, 4 * 64 * 65 * 4);

    probe_kernel<<<1, 32>>>(emb_t);
    const int CB = 2048, CT = 256;
    const long SZD = (long)DD * DD;
    const long SZF = (long)DFFN * DD;
    for (int l = 0; l < LLAY; l++) {
        convert_wb<<<CB, CT>>>(qt, qs, l * SZD, OQKV + (long)l * 3 * SZD,           SZD);
        convert_wb<<<CB, CT>>>(kt, ks, l * SZD, OQKV + (long)l * 3 * SZD + SZD,     SZD);
        convert_wb<<<CB, CT>>>(vt, vs, l * SZD, OQKV + (long)l * 3 * SZD + 2 * SZD, SZD);
        convert_wb<<<CB, CT>>>(gt, gs, l * SZF, OGU  + (long)l * 2 * SZF,           SZF);
        convert_wb<<<CB, CT>>>(ut, us, l * SZF, OGU  + (long)l * 2 * SZF + SZF,     SZF);
    }
    convert_wb<<<CB, CT>>>(ot, os, 0, OO,  (long)LLAY * SZD);
    convert_wb<<<CB, CT>>>(dt, ds, 0, ODW, (long)LLAY * SZF);
    convert_wb<<<CB, CT>>>(ht, hs, 0, OHD, (long)VV * DD);

    embed_kernel<<<MM, 256>>>(ids, emb_t, emb_s, x);

    const bf16* WL = wb + WTOT;
    const size_t smem = 2 * STG_B;
    const size_t asmem = 4 * 64 * 65 * 4;

    for (int l = 0; l < LLAY; l++) {
        long oqkv = OQKV + (long)l * 3 * SZD;
        long oo   = OO   + (long)l * SZD;
        long ogu  = OGU  + (long)l * 2 * SZF;
        long odw  = ODW  + (long)l * SZF;

        rmsnorm_split<<<MM, 256>>>(x, wa + (long)l * DD, h, hhi, hlo);
        gemm3_kernel<false><<<dim3(24, 16), 256, smem>>>(hhi, hlo, wb + oqkv, WL + oqkv, qkv, MM, 3 * DD, DD);
        attn_flash<<<dim3(SS / 64, BB * HH), 256, asmem>>>(qkv, h, alpha + (long)l * HH, ohi, olo);
        gemm3_kernel<true><<<dim3(8, 16), 256, smem>>>(ohi, olo, wb + oo, WL + oo, x, MM, DD, DD);

        rmsnorm_split<<<MM, 256>>>(x, wm + (long)l * DD, nullptr, hhi, hlo);
        gemm3_kernel<false><<<dim3(64, 16), 256, smem>>>(hhi, hlo, wb + ogu, WL + ogu, gu, MM, 2 * DFFN, DD);
        silumul_split<<<(long)MM * DFFN / 256, 256>>>(gu, ghi, glo);
        gemm3_kernel<true><<<dim3(8, 16), 256, smem>>>(ghi, glo, wb + odw, WL + odw, x, MM, DD, DFFN);
    }

    rmsnorm_split<<<MM, 256>>>(x, wf, nullptr, hhi, hlo);
    gemm3_kernel<false><<<dim3(VV / 128, 16), 256, smem>>>(hhi, hlo, wb + OHD, WL + OHD, out, MM, VV, DD);
}

// round 11
// speedup vs baseline: 6.1599x; 1.1260x over previous
#include <cuda_runtime.h>
#include <cuda_bf16.h>
#include <cstdint>

using bf16 = __nv_bfloat16;

// ---------------- problem dims ----------------
#define BB   2
#define SS   1024
#define DD   1024
#define HH   16
#define DFFN 4096
#define LLAY 2
#define VV   32000
#define MM   (BB*SS)

// ---------------- ternary weight buffer (bf16, EXACT codes) ----------------
#define OQKV 0L
#define OO   (OQKV + (long)LLAY*3*DD*DD)
#define OGU  (OO   + (long)LLAY*DD*DD)
#define ODW  (OGU  + (long)LLAY*2*DFFN*DD)
#define OHD  (ODW  + (long)LLAY*DD*DFFN)
#define WTOT (OHD  + (long)VV*DD)

__device__ bf16  g_wt[WTOT];          // ternary codes as bf16 (exact)
__device__ float g_sc[WTOT/128];      // per-group scales, packed to match g_wt
__device__ int   g_wtype;

// ---------------- activation scratch ----------------
__device__ float g_x[MM*DD];
__device__ float g_h[MM*DD];
__device__ float g_qkv[(size_t)MM*3*DD];
__device__ float g_gu[(size_t)MM*2*DFFN];
__device__ bf16  g_hhi[MM*DD],  g_hlo[MM*DD];
__device__ bf16  g_ohi[MM*DD],  g_olo[MM*DD];
__device__ bf16  g_ghi[(size_t)MM*DFFN], g_glo[(size_t)MM*DFFN];

// ---------------- dtype probe ----------------
__global__ void probe_kernel(const void* raw) {
    if (threadIdx.x != 0) return;
    const unsigned* pw = (const unsigned*)raw;
    bool is_i32 = true;
    for (int i = 0; i < 256; i++) {
        unsigned w = pw[i];
        if (!(w == 0u || w == 1u || w == 0xFFFFFFFFu)) { is_i32 = false; break; }
    }
    if (is_i32) { g_wtype = 1; return; }
    bool is_f32 = true;
    for (int i = 0; i < 256; i++) {
        unsigned w = pw[i];
        if (!(w == 0u || w == 0x3F800000u || w == 0xBF800000u)) { is_f32 = false; break; }
    }
    if (is_f32) { g_wtype = 2; return; }
    const unsigned short* ph = (const unsigned short*)raw;
    bool is_b16 = true;
    for (int i = 0; i < 512; i++) {
        unsigned short w = ph[i];
        if (!(w == 0u || w == 0x3F80u || w == 0xBF80u)) { is_b16 = false; break; }
    }
    g_wtype = is_b16 ? 3 : 0;
}

__device__ __forceinline__ float load_tern(const void* p, long i, int t) {
    if (t == 1) return (float)((const int*)p)[i];
    if (t == 2) return ((const float*)p)[i];
    if (t == 3) return __bfloat162float(((const bf16*)p)[i]);
    return (float)((const int8_t*)p)[i];
}

// ---------------- weight convert: exact int -> bf16 (vectorized for int32 src) ----------------
struct alignas(16) B8 { bf16 v[8]; };

__global__ void convert_t(const void* __restrict__ src, long srcOff, long dstOff, long n) {
    int t = g_wtype;
    if (t == 1) {
        long stride = (long)gridDim.x * blockDim.x * 8;
        for (long i = ((long)blockIdx.x * blockDim.x + threadIdx.x) * 8; i < n; i += stride) {
            const int4* p = (const int4*)((const int*)src + srcOff + i);
            int4 a = p[0], b = p[1];
            B8 o;
            o.v[0] = __float2bfloat16((float)a.x); o.v[1] = __float2bfloat16((float)a.y);
            o.v[2] = __float2bfloat16((float)a.z); o.v[3] = __float2bfloat16((float)a.w);
            o.v[4] = __float2bfloat16((float)b.x); o.v[5] = __float2bfloat16((float)b.y);
            o.v[6] = __float2bfloat16((float)b.z); o.v[7] = __float2bfloat16((float)b.w);
            *(B8*)(g_wt + dstOff + i) = o;
        }
    } else {
        long stride = (long)gridDim.x * blockDim.x;
        for (long i = (long)blockIdx.x * blockDim.x + threadIdx.x; i < n; i += stride)
            g_wt[dstOff + i] = __float2bfloat16(load_tern(src, srcOff + i, t));
    }
}

// ---------------- scale copy into packed layout ----------------
__global__ void copy_sc(const float* __restrict__ src, long srcOff, long dstOff, long n) {
    long stride = (long)gridDim.x * blockDim.x * 4;
    for (long i = ((long)blockIdx.x * blockDim.x + threadIdx.x) * 4; i < n; i += stride) {
        float4 v = *(const float4*)(src + srcOff + i);
        *(float4*)(g_sc + dstOff + i) = v;
    }
}

// ---------------- embedding ----------------
__global__ void embed_kernel(const int* __restrict__ ids, const void* __restrict__ et,
                             const float* __restrict__ es, float* __restrict__ x) {
    int t = g_wtype;
    int m = blockIdx.x;
    long base = (long)ids[m] * DD;
    for (int d = threadIdx.x; d < DD; d += blockDim.x) {
        long idx = base + d;
        x[(long)m * DD + d] = load_tern(et, idx, t) * es[idx >> 7];
    }
}

// ---------------- rmsnorm + hi/lo split ----------------
__global__ void rmsnorm_split(const float* __restrict__ x, const float* __restrict__ w,
                              float* __restrict__ h, bf16* __restrict__ hi, bf16* __restrict__ lo) {
    int m = blockIdx.x;
    const float* xr = x + (long)m * DD;
    float ss = 0.f;
    for (int d = threadIdx.x; d < DD; d += blockDim.x) { float v = xr[d]; ss += v * v; }
    __shared__ float red[256];
    red[threadIdx.x] = ss; __syncthreads();
    #pragma unroll
    for (int st = 128; st > 0; st >>= 1) {
        if (threadIdx.x < st) red[threadIdx.x] += red[threadIdx.x + st];
        __syncthreads();
    }
    float r = rsqrtf(red[0] * (1.0f / DD) + 1e-6f);
    for (int d = threadIdx.x; d < DD; d += blockDim.x) {
        long i = (long)m * DD + d;
        float y = xr[d] * r * w[d];
        if (h) h[i] = y;
        bf16 yh = __float2bfloat16(y);
        hi[i] = yh;
        lo[i] = __float2bfloat16(y - __bfloat162float(yh));
    }
}

// ---------------- mma.sync helpers ----------------
__device__ __forceinline__ void cpa16(uint32_t d, const void* s) {
    asm volatile("cp.async.ca.shared.global [%0], [%1], 16;\n" :: "r"(d), "l"(s));
}
__device__ __forceinline__ void ldsm4(uint32_t* r, uint32_t a) {
    asm volatile("ldmatrix.sync.aligned.m8n8.x4.shared.b16 {%0,%1,%2,%3},[%4];"
                 : "=r"(r[0]), "=r"(r[1]), "=r"(r[2]), "=r"(r[3]) : "r"(a));
}
__device__ __forceinline__ void ldsm2(uint32_t* r, uint32_t a) {
    asm volatile("ldmatrix.sync.aligned.m8n8.x2.shared.b16 {%0,%1},[%2];"
                 : "=r"(r[0]), "=r"(r[1]) : "r"(a));
}
__device__ __forceinline__ void mma16816(float* c, const uint32_t* a, const uint32_t* b) {
    asm volatile("mma.sync.aligned.m16n8k16.row.col.f32.bf16.bf16.f32 "
                 "{%0,%1,%2,%3},{%4,%5,%6,%7},{%8,%9},{%0,%1,%2,%3};"
                 : "+f"(c[0]), "+f"(c[1]), "+f"(c[2]), "+f"(c[3])
                 : "r"(a[0]), "r"(a[1]), "r"(a[2]), "r"(a[3]), "r"(b[0]), "r"(b[1]));
}

// ---------------- 2-product group-scaled GEMM ----------------
// C[M,N] (+)= sum_g s[n,g] * sum_{k in g} (Ahi+Alo)[m,k] * T[n,k]
// BM=BN=128, BK=32, 512 threads (16 warps, 32x32 warp tiles), 4-stage cp.async.
#define STG2_B 30720          // Ah(10240) + Al(10240) + T(10240), rows padded to 40 elems
#define NSTG   4
#define GSM2   (NSTG*STG2_B)  // 122880

template<bool ACCF>
__global__ __launch_bounds__(512, 1)
void gemm2_kernel(const bf16* __restrict__ Ah, const bf16* __restrict__ Al,
                  const bf16* __restrict__ T,  const float* __restrict__ sc,
                  float* __restrict__ C, int M, int N, int K) {
    extern __shared__ char smem_raw[];
    const uint32_t sbase = (uint32_t)__cvta_generic_to_shared(smem_raw);
    const int tid = threadIdx.x, lane = tid & 31, wid = tid >> 5;
    const int wm = wid >> 2, wn = wid & 3;
    const int bm = blockIdx.y * 128, bn = blockIdx.x * 128;
    const int Kg = K >> 7;
    const int r0 = tid >> 2, cc = (tid & 3) * 8;

    int aoffE[2], boffE[4];
    {
        int r = lane & 15, kh = (lane >> 4) * 8;
        #pragma unroll
        for (int mi = 0; mi < 2; mi++) aoffE[mi] = (wm * 32 + mi * 16 + r) * 40 + kh;
        #pragma unroll
        for (int ni = 0; ni < 4; ni++) boffE[ni] = (wn * 32 + ni * 8 + (r & 7)) * 40 + ((r >> 3) * 8);
    }

    float accM[2][4][4], accP[2][4][4];
    #pragma unroll
    for (int i = 0; i < 2; i++)
        #pragma unroll
        for (int j = 0; j < 4; j++)
            #pragma unroll
            for (int c = 0; c < 4; c++) { accM[i][j][c] = 0.f; accP[i][j][c] = 0.f; }

    auto load_stage = [&](int kt) {
        uint32_t sb = sbase + (kt & (NSTG - 1)) * STG2_B;
        uint32_t d = r0 * 80 + cc * 2;
        size_t ga = (size_t)(bm + r0) * K + (size_t)kt * 32 + cc;
        size_t gb = (size_t)(bn + r0) * K + (size_t)kt * 32 + cc;
        cpa16(sb + d,         Ah + ga);
        cpa16(sb + 10240 + d, Al + ga);
        cpa16(sb + 20480 + d, T + gb);
    };

    const int KT = K >> 5;
    load_stage(0); asm volatile("cp.async.commit_group;\n" ::: "memory");
    load_stage(1); asm volatile("cp.async.commit_group;\n" ::: "memory");
    load_stage(2); asm volatile("cp.async.commit_group;\n" ::: "memory");

    for (int kt = 0; kt < KT; kt++) {
        asm volatile("cp.async.wait_group 2;\n" ::: "memory");
        __syncthreads();
        if (kt + 3 < KT) load_stage(kt + 3);
        asm volatile("cp.async.commit_group;\n" ::: "memory");

        uint32_t sb = sbase + (kt & (NSTG - 1)) * STG2_B;
        #pragma unroll
        for (int kk = 0; kk < 2; kk++) {
            const int kb = kk * 32;
            uint32_t a[2][4], b[4][2];
            #pragma unroll
            for (int ni = 0; ni < 4; ni++) ldsm2(b[ni], sb + 20480 + boffE[ni] * 2 + kb);
            #pragma unroll
            for (int mi = 0; mi < 2; mi++) ldsm4(a[mi], sb + aoffE[mi] * 2 + kb);
            #pragma unroll
            for (int mi = 0; mi < 2; mi++)
                #pragma unroll
                for (int ni = 0; ni < 4; ni++) mma16816(accP[mi][ni], a[mi], b[ni]);
            #pragma unroll
            for (int mi = 0; mi < 2; mi++) ldsm4(a[mi], sb + 10240 + aoffE[mi] * 2 + kb);
            #pragma unroll
            for (int mi = 0; mi < 2; mi++)
                #pragma unroll
                for (int ni = 0; ni < 4; ni++) mma16816(accP[mi][ni], a[mi], b[ni]);
        }

        if ((kt & 3) == 3) {   // 128-K group boundary: fold with fp32 scale
            int g = kt >> 2;
            #pragma unroll
            for (int ni = 0; ni < 4; ni++) {
                int col = bn + wn * 32 + ni * 8 + (lane & 3) * 2;
                float s0 = __ldg(sc + (size_t)col * Kg + g);
                float s1 = __ldg(sc + (size_t)(col + 1) * Kg + g);
                #pragma unroll
                for (int mi = 0; mi < 2; mi++) {
                    accM[mi][ni][0] += s0 * accP[mi][ni][0];
                    accM[mi][ni][1] += s1 * accP[mi][ni][1];
                    accM[mi][ni][2] += s0 * accP[mi][ni][2];
                    accM[mi][ni][3] += s1 * accP[mi][ni][3];
                    accP[mi][ni][0] = 0.f; accP[mi][ni][1] = 0.f;
                    accP[mi][ni][2] = 0.f; accP[mi][ni][3] = 0.f;
                }
            }
        }
    }

    #pragma unroll
    for (int mi = 0; mi < 2; mi++) {
        int row = bm + wm * 32 + mi * 16 + (lane >> 2);
        #pragma unroll
        for (int ni = 0; ni < 4; ni++) {
            int col = bn + wn * 32 + ni * 8 + (lane & 3) * 2;
            float* p0 = C + (size_t)row * N + col;
            float* p1 = p0 + (size_t)8 * N;
            if (ACCF) {
                p0[0] += accM[mi][ni][0]; p0[1] += accM[mi][ni][1];
                p1[0] += accM[mi][ni][2]; p1[1] += accM[mi][ni][3];
            } else {
                p0[0] = accM[mi][ni][0]; p0[1] = accM[mi][ni][1];
                p1[0] = accM[mi][ni][2]; p1[1] = accM[mi][ni][3];
            }
        }
    }
}

// ---------------- flash-style tiled causal attention ----------------
__device__ __forceinline__ float rmax16(float v) {
    #pragma unroll
    for (int m = 1; m < 16; m <<= 1) v = fmaxf(v, __shfl_xor_sync(0xffffffffu, v, m));
    return v;
}
__device__ __forceinline__ float rsum16(float v) {
    #pragma unroll
    for (int m = 1; m < 16; m <<= 1) v += __shfl_xor_sync(0xffffffffu, v, m);
    return v;
}

__global__ __launch_bounds__(256)
void attn_flash(const float* __restrict__ qkv, const float* __restrict__ h,
                const float* __restrict__ alpha, bf16* __restrict__ ohi, bf16* __restrict__ olo) {
    extern __shared__ float sm[];
    float (*Qs)[65] = (float(*)[65])sm;
    float (*Ks)[65] = (float(*)[65])(sm + 64 * 65);
    float (*Vs)[65] = (float(*)[65])(sm + 2 * 64 * 65);
    float (*Ps)[65] = (float(*)[65])(sm + 3 * 64 * 65);

    int qt = blockIdx.x;
    int bh = blockIdx.y;
    int b = bh >> 4, hh = bh & 15;
    int tid = threadIdx.x;
    int tx = tid & 15, ty = tid >> 4;

    const float* qb = qkv + (size_t)(b * SS + qt * 64) * 3072 + hh * 64;
    for (int i = tid; i < 64 * 64; i += 256)
        Qs[i >> 6][i & 63] = qb[(size_t)(i >> 6) * 3072 + (i & 63)];

    float m_run[4], l_run[4], O[4][4];
    #pragma unroll
    for (int i = 0; i < 4; i++) {
        m_run[i] = -3.4e38f; l_run[i] = 0.f;
        O[i][0] = O[i][1] = O[i][2] = O[i][3] = 0.f;
    }

    const float* kb = qkv + (size_t)b * SS * 3072 + 1024 + hh * 64;
    const float* vb = qkv + (size_t)b * SS * 3072 + 2048 + hh * 64;

    for (int kt = 0; kt <= qt; kt++) {
        __syncthreads();
        for (int i = tid; i < 64 * 64; i += 256) {
            int r = i >> 6, c = i & 63;
            size_t gr = (size_t)(kt * 64 + r) * 3072 + c;
            Ks[r][c] = kb[gr];
            Vs[r][c] = vb[gr];
        }
        __syncthreads();

        float s[4][4];
        #pragma unroll
        for (int i = 0; i < 4; i++) { s[i][0]=0.f; s[i][1]=0.f; s[i][2]=0.f; s[i][3]=0.f; }
        #pragma unroll 8
        for (int d = 0; d < 64; d++) {
            float a[4], bv[4];
            #pragma unroll
            for (int i = 0; i < 4; i++) a[i]  = Qs[ty * 4 + i][d];
            #pragma unroll
            for (int j = 0; j < 4; j++) bv[j] = Ks[tx * 4 + j][d];
            #pragma unroll
            for (int i = 0; i < 4; i++)
                #pragma unroll
                for (int j = 0; j < 4; j++) s[i][j] += a[i] * bv[j];
        }
        if (kt == qt) {
            #pragma unroll
            for (int i = 0; i < 4; i++) {
                int row = ty * 4 + i;
                #pragma unroll
                for (int j = 0; j < 4; j++)
                    if (tx * 4 + j > row) s[i][j] = -3.4e38f;
        } }
        #pragma unroll
        for (int i = 0; i < 4; i++) {
            float tm = fmaxf(fmaxf(s[i][0] * 0.125f, s[i][1] * 0.125f),
                             fmaxf(s[i][2] * 0.125f, s[i][3] * 0.125f));
            tm = rmax16(tm);
            float m_new = fmaxf(m_run[i], tm);
            float fac = expf(m_run[i] - m_new);
            float rs = 0.f;
            #pragma unroll
            for (int j = 0; j < 4; j++) {
                float p = expf(s[i][j] * 0.125f - m_new);
                Ps[ty * 4 + i][tx * 4 + j] = p;
                rs += p;
            }
            rs = rsum16(rs);
            l_run[i] = l_run[i] * fac + rs;
            m_run[i] = m_new;
            #pragma unroll
            for (int j = 0; j < 4; j++) O[i][j] *= fac;
        }
        __syncthreads();

        #pragma unroll 8
        for (int t = 0; t < 64; t++) {
            float a[4], bv[4];
            #pragma unroll
            for (int i = 0; i < 4; i++) a[i]  = Ps[ty * 4 + i][t];
            #pragma unroll
            for (int j = 0; j < 4; j++) bv[j] = Vs[t][tx * 4 + j];
            #pragma unroll
            for (int i = 0; i < 4; i++)
                #pragma unroll
                for (int j = 0; j < 4; j++) O[i][j] += a[i] * bv[j];
        }
    }

    float ah = alpha[hh];
    #pragma unroll
    for (int i = 0; i < 4; i++) {
        float inv = 1.f / l_run[i];
        int row = qt * 64 + ty * 4 + i;
        #pragma unroll
        for (int j = 0; j < 4; j++) {
            long idx = (long)(b * SS + row) * DD + hh * 64 + tx * 4 + j;
            float val = O[i][j] * inv + ah * h[idx];
            bf16 vh = __float2bfloat16(val);
            ohi[idx] = vh;
            olo[idx] = __float2bfloat16(val - __bfloat162float(vh));
        }
    }
}

// ---------------- silu(g)*u, split (vectorized x4) ----------------
struct alignas(8) B4 { bf16 v[4]; };
__global__ void silumul_split(const float* __restrict__ gu, bf16* __restrict__ ghi, bf16* __restrict__ glo) {
    long i = ((long)blockIdx.x * 256 + threadIdx.x) * 4;
    long m = i >> 12, j = i & 4095;
    float4 a4 = *(const float4*)(gu + (m << 13) + j);
    float4 u4 = *(const float4*)(gu + (m << 13) + 4096 + j);
    float av[4] = {a4.x, a4.y, a4.z, a4.w};
    float uv[4] = {u4.x, u4.y, u4.z, u4.w};
    B4 hi, lo;
    #pragma unroll
    for (int c = 0; c < 4; c++) {
        float val = av[c] / (1.f + expf(-av[c])) * uv[c];
        bf16 vh = __float2bfloat16(val);
        hi.v[c] = vh;
        lo.v[c] = __float2bfloat16(val - __bfloat162float(vh));
    }
    *(B4*)(ghi + i) = hi;
    *(B4*)(glo + i) = lo;
}

// ---------------- host launcher ----------------
extern "C" void kernel_launch(void* const* d_in, const int* in_sizes, int n_in,
                              void* d_out, int out_size) {
    (void)in_sizes; (void)n_in; (void)out_size;
    const int*   ids   = (const int*)  d_in[0];
    const void*  emb_t = d_in[1];
    const float* emb_s = (const float*)d_in[2];
    const void*  qt = d_in[3];  const float* qs = (const float*)d_in[4];
    const void*  kt = d_in[5];  const float* ks = (const float*)d_in[6];
    const void*  vt = d_in[7];  const float* vs = (const float*)d_in[8];
    const void*  ot = d_in[9];  const float* os = (const float*)d_in[10];
    const void*  gt = d_in[11]; const float* gs = (const float*)d_in[12];
    const void*  ut = d_in[13]; const float* us = (const float*)d_in[14];
    const void*  dt = d_in[15]; const float* ds = (const float*)d_in[16];
    const float* wa    = (const float*)d_in[17];
    const float* wm    = (const float*)d_in[18];
    const float* alpha = (const float*)d_in[19];
    const float* wf    = (const float*)d_in[20];
    const void*  ht = d_in[21]; const float* hs = (const float*)d_in[22];
    float* out = (float*)d_out;

    float *x, *h, *qkv, *gu, *scb;
    bf16 *wt, *hhi, *hlo, *ohi, *olo, *ghi, *glo;
    cudaGetSymbolAddress((void**)&x,   g_x);
    cudaGetSymbolAddress((void**)&h,   g_h);
    cudaGetSymbolAddress((void**)&qkv, g_qkv);
    cudaGetSymbolAddress((void**)&gu,  g_gu);
    cudaGetSymbolAddress((void**)&wt,  g_wt);
    cudaGetSymbolAddress((void**)&scb, g_sc);
    cudaGetSymbolAddress((void**)&hhi, g_hhi);
    cudaGetSymbolAddress((void**)&hlo, g_hlo);
    cudaGetSymbolAddress((void**)&ohi, g_ohi);
    cudaGetSymbolAddress((void**)&olo, g_olo);
    cudaGetSymbolAddress((void**)&ghi, g_ghi);
    cudaGetSymbolAddress((void**)&glo, g_glo);

    cudaFuncSetAttribute(gemm2_kernel<false>, cudaFuncAttributeMaxDynamicSharedMemorySize, GSM2);
    cudaFuncSetAttribute(gemm2_kernel<true>,  cudaFuncAttributeMaxDynamicSharedMemorySize, GSM2);
    cudaFuncSetAttribute(attn_flash, cudaFuncAttributeMaxDynamicSharedMemorySize, 4 * 64 * 65 * 4);

    probe_kernel<<<1, 32>>>(emb_t);

    const long SZD = (long)DD * DD;       // 1,048,576
    const long SZF = (long)DFFN * DD;     // 4,194,304
    const long ngD = SZD / 128, ngF = SZF / 128;

    // weights -> exact bf16 codes
    for (int l = 0; l < LLAY; l++) {
        convert_t<<<1024, 256>>>(qt, l * SZD, OQKV + (long)l * 3 * SZD,           SZD);
        convert_t<<<1024, 256>>>(kt, l * SZD, OQKV + (long)l * 3 * SZD + SZD,     SZD);
        convert_t<<<1024, 256>>>(vt, l * SZD, OQKV + (long)l * 3 * SZD + 2 * SZD, SZD);
        convert_t<<<1024, 256>>>(gt, l * SZF, OGU  + (long)l * 2 * SZF,           SZF);
        convert_t<<<1024, 256>>>(ut, l * SZF, OGU  + (long)l * 2 * SZF + SZF,     SZF);
    }
    convert_t<<<1024, 256>>>(ot, 0, OO,  (long)LLAY * SZD);
    convert_t<<<1024, 256>>>(dt, 0, ODW, (long)LLAY * SZF);
    convert_t<<<2048, 256>>>(ht, 0, OHD, (long)VV * DD);

    // scales -> packed layout matching g_wt
    for (int l = 0; l < LLAY; l++) {
        copy_sc<<<64, 256>>>(qs, l * ngD, (OQKV + (long)l * 3 * SZD) / 128,           ngD);
        copy_sc<<<64, 256>>>(ks, l * ngD, (OQKV + (long)l * 3 * SZD + SZD) / 128,     ngD);
        copy_sc<<<64, 256>>>(vs, l * ngD, (OQKV + (long)l * 3 * SZD + 2 * SZD) / 128, ngD);
        copy_sc<<<64, 256>>>(gs, l * ngF, (OGU + (long)l * 2 * SZF) / 128,            ngF);
        copy_sc<<<64, 256>>>(us, l * ngF, (OGU + (long)l * 2 * SZF + SZF) / 128,      ngF);
    }
    copy_sc<<<64, 256>>>(os, 0, OO / 128,  (long)LLAY * ngD);
    copy_sc<<<128, 256>>>(ds, 0, ODW / 128, (long)LLAY * ngF);
    copy_sc<<<256, 256>>>(hs, 0, OHD / 128, (long)VV * DD / 128);

    embed_kernel<<<MM, 256>>>(ids, emb_t, emb_s, x);

    const size_t asmem = 4 * 64 * 65 * 4;

    for (int l = 0; l < LLAY; l++) {
        long oqkv = OQKV + (long)l * 3 * SZD;
        long oo   = OO   + (long)l * SZD;
        long ogu  = OGU  + (long)l * 2 * SZF;
        long odw  = ODW  + (long)l * SZF;

        rmsnorm_split<<<MM, 256>>>(x, wa + (long)l * DD, h, hhi, hlo);
        gemm2_kernel<false><<<dim3(24, 16), 512, GSM2>>>(hhi, hlo, wt + oqkv, scb + oqkv / 128, qkv, MM, 3 * DD, DD);
        attn_flash<<<dim3(SS / 64, BB * HH), 256, asmem>>>(qkv, h, alpha + (long)l * HH, ohi, olo);
        gemm2_kernel<true><<<dim3(8, 16), 512, GSM2>>>(ohi, olo, wt + oo, scb + oo / 128, x, MM, DD, DD);

        rmsnorm_split<<<MM, 256>>>(x, wm + (long)l * DD, nullptr, hhi, hlo);
        gemm2_kernel<false><<<dim3(64, 16), 512, GSM2>>>(hhi, hlo, wt + ogu, scb + ogu / 128, gu, MM, 2 * DFFN, DD);
        silumul_split<<<(long)MM * DFFN / 1024, 256>>>(gu, ghi, glo);
        gemm2_kernel<true><<<dim3(8, 16), 512, GSM2>>>(ghi, glo, wt + odw, scb + odw / 128, x, MM, DD, DFFN);
    }

    rmsnorm_split<<<MM, 256>>>(x, wf, nullptr, hhi, hlo);
    gemm2_kernel<false><<<dim3(VV / 128, 16), 512, GSM2>>>(hhi, hlo, wt + OHD, scb + OHD / 128, out, MM, VV, DD);
}